// round 15
// baseline (speedup 1.0000x reference)
#include <cuda_runtime.h>
#include <cuda_fp16.h>

#define N_NODES 50000
#define N_EDGES 800000
#define D 64
#define BN_EPS 1e-5f
#define THREADS 256
#define WPB 8
#define NB_F 592             // 148 SMs * 4 CTAs
#define ROWS 4               // rows per warp per group
#define NGROUPS (N_NODES / ROWS)   // 12500
#define HS_B 592             // build kernel grid (all-resident: 148*4)
#define SCAN_BLK 196         // 196*256 >= N_NODES
#define MAXE 6               // ceil(N_EDGES / (HS_B*256))

typedef unsigned long long ull;

// packed f32x2 helpers (sm_103a FFMA2 path)
#define FMA2(o, a, b, c) asm("fma.rn.f32x2 %0, %1, %2, %3;" : "=l"(o) : "l"(a), "l"(b), "l"(c))
#define ADD2(o, a, b)    asm("add.rn.f32x2 %0, %1, %2;"     : "=l"(o) : "l"(a), "l"(b))
#define PACK2(o, lo, hi) asm("mov.b64 %0, {%1, %2};"        : "=l"(o) : "r"(lo), "r"(hi))
#define UNPK2(lo, hi, i) asm("mov.b64 {%0, %1}, %2;"        : "=r"(lo), "=r"(hi) : "l"(i))

// ---------------- scratch (static device allocations; no cudaMalloc) --------
__device__ int      g_rowstart[N_NODES + 1];
__device__ int      g_cursor[N_NODES];
__device__ int      g_esrc[N_EDGES];
__device__ float    g_y[N_NODES * D];
__device__ float    g_partial[NB_F * 128];
__device__ int      g_blocksum[SCAN_BLK];
__device__ unsigned g_bar[4];                  // grid-barrier counters
__device__ __align__(128) __half2 g_g16[N_NODES * 32];  // fp16 gather source
__device__ __align__(16) float g_bnscale[D];
__device__ __align__(16) float g_bnshift[D];

// ---------------- grid barrier: atomic arrive, volatile-load poll -----------
__device__ __forceinline__ void grid_bar(int idx) {
    __syncthreads();
    if (threadIdx.x == 0) {
        __threadfence();
        atomicAdd(&g_bar[idx], 1u);
        volatile unsigned* p = &g_bar[idx];
        while (*p < (unsigned)HS_B) { }
    }
    __syncthreads();
    __threadfence();
}

// ------- build: detect dtype + zero + cvt16 + hist + scan + scatter ---------
__global__ void __launch_bounds__(256, 4) build_kernel(const void* ei,
                                                       const float* __restrict__ x) {
    const int* p32 = (const int*)ei;
    int tid = threadIdx.x, b = blockIdx.x;
    const int gstride = HS_B * 256;
    int gt = b * 256 + tid;

    // phase 0a: detect edge dtype locally (redundant per CTA, L2-broadcast)
    __shared__ int s_i32;
    if (tid == 0) s_i32 = 0;
    __syncthreads();
    for (int i = tid; i < 1024; i += 256)
        if (p32[2 * i + 1] != 0) s_i32 = 1;    // benign race

    // phase 0b: zero rowstart; set sentinel
    for (int i = gt; i < N_NODES; i += gstride) g_rowstart[i] = 0;
    if (gt == 0) g_rowstart[N_NODES] = N_EDGES;

    // phase 0c: cvt x -> fp16 (independent work hidden before barrier)
    {
        const float2* s2 = (const float2*)x;
        for (int i = gt; i < N_NODES * 32; i += gstride)
            g_g16[i] = __float22half2_rn(s2[i]);
    }
    __syncthreads();
    const bool i64 = (s_i32 == 0);
    grid_bar(0);

    // phase 1: histogram of dst; cache src+dst in registers
    int dcache[MAXE], scache[MAXE];
#pragma unroll
    for (int k = 0; k < MAXE; k++) {
        int e = gt + k * gstride;
        if (e < N_EDGES) {
            int d = i64 ? p32[2 * (N_EDGES + e)] : p32[N_EDGES + e];
            int s = i64 ? p32[2 * e]             : p32[e];
            dcache[k] = d; scache[k] = s;
            atomicAdd(&g_rowstart[d], 1);
        }
    }
    grid_bar(1);

    // phase 2: per-block local scan of 256 degrees + publish block sum
    __shared__ int wsum[8];
    __shared__ int sbs[SCAN_BLK];
    __shared__ int blockoff_s;
    int excl_local = 0;
    if (b < SCAN_BLK) {
        int i = b * 256 + tid;
        int v = (i < N_NODES) ? g_rowstart[i] : 0;
        int lane = tid & 31, w = tid >> 5;
        int inc = v;
#pragma unroll
        for (int off = 1; off < 32; off <<= 1) {
            int n = __shfl_up_sync(~0u, inc, off);
            if (lane >= off) inc += n;
        }
        if (lane == 31) wsum[w] = inc;
        __syncthreads();
        if (w == 0) {
            int s = (lane < 8) ? wsum[lane] : 0;
#pragma unroll
            for (int off = 1; off < 8; off <<= 1) {
                int n = __shfl_up_sync(~0u, s, off);
                if (lane >= off) s += n;
            }
            if (lane < 8) wsum[lane] = s;
        }
        __syncthreads();
        int warpoff = (w == 0) ? 0 : wsum[w - 1];
        excl_local = warpoff + inc - v;
        if (tid == 0) g_blocksum[b] = wsum[7];
    }
    grid_bar(2);

    // phase 3: block offset + write rowstart/cursor
    if (b < SCAN_BLK) {
        for (int j = tid; j < SCAN_BLK; j += 256) sbs[j] = g_blocksum[j];
        __syncthreads();
        if (tid == 0) {
            int o = 0;
            for (int j = 0; j < b; j++) o += sbs[j];
            blockoff_s = o;
        }
        __syncthreads();
        int i = b * 256 + tid;
        if (i < N_NODES) {
            int e0 = blockoff_s + excl_local;
            g_rowstart[i] = e0;
            g_cursor[i]   = e0;
        }
    }
    grid_bar(3);

    // phase 4: scatter cached src ids into CSR order
#pragma unroll
    for (int k = 0; k < MAXE; k++) {
        int e = gt + k * gstride;
        if (e < N_EDGES) {
            int pos = atomicAdd(&g_cursor[dcache[k]], 1);
            g_esrc[pos] = scache[k];
        }
    }
}

// convert 8B (2 half2 = 4 cols) and accumulate into two packed f32 pairs
__device__ __forceinline__ void acc8(ull v, ull& alo, ull& ahi) {
    unsigned lo32 = (unsigned)v, hi32 = (unsigned)(v >> 32);
    __half2 hl = *(__half2*)&lo32, hh = *(__half2*)&hi32;
    float2 f0 = __half22float2(hl), f1 = __half22float2(hh);
    ull u0, u1;
    PACK2(u0, __float_as_uint(f0.x), __float_as_uint(f0.y));
    PACK2(u1, __float_as_uint(f1.x), __float_as_uint(f1.y));
    ADD2(alo, alo, u0);
    ADD2(ahi, ahi, u1);
}

// ---- GEMM core: 4 rows per warp, h in registers, shuffle broadcast ---------
__device__ __forceinline__ void warp_gemm4(const ull* __restrict__ Ws, ull bb,
                                           const float* ax, const float* ay,
                                           ull* acc, int lane) {
    acc[0] = bb; acc[1] = bb; acc[2] = bb; acc[3] = bb;
#pragma unroll
    for (int k = 0; k < D; k++) {
        ull wv = Ws[k * 32 + lane];
#pragma unroll
        for (int r = 0; r < ROWS; r++) {
            float hv = __shfl_sync(~0u, (k & 1) ? ay[r] : ax[r], k >> 1);
            unsigned hu = __float_as_uint(hv);
            ull h2; PACK2(h2, hu, hu);
            FMA2(acc[r], h2, wv, acc[r]);
        }
    }
}

// ---------------- K1: paired-lane fp16 gather + GEMM W1 + BN partials -------
__global__ void __launch_bounds__(THREADS, 4)
gin_fused1(const float* __restrict__ xin, const float* __restrict__ W1,
           const float* __restrict__ b1) {
    __shared__ ull Ws[D * 32];
    __shared__ float ssum[WPB][D];
    __shared__ float ssq[WPB][D];
    int tid = threadIdx.x, w = tid >> 5, lane = tid & 31;
    int half = lane >> 4, p = lane & 15;

    const ull* W1p = (const ull*)W1;
    for (int i = tid; i < D * 32; i += THREADS) Ws[i] = W1p[i];
    ull bb = ((const ull*)b1)[lane];
    __syncthreads();

    const ull* x2 = (const ull*)xin;
    const ull* gu = (const ull*)g_g16;   // gu[row*16+p] = cols 4p..4p+3 (fp16)
    ull*       y2 = (ull*)g_y;

    float s0 = 0.f, s1 = 0.f, q0 = 0.f, q1 = 0.f;
    int gid0 = blockIdx.x * WPB + w;
    const int GSTRIDE = NB_F * WPB;      // 4736

    for (int gid = gid0; gid < NGROUPS; gid += GSTRIDE) {
        int row0 = gid * ROWS;
        float ax[ROWS], ay[ROWS];

#pragma unroll
        for (int r = 0; r < ROWS; r++) {
            int row = row0 + r;
            int beg = g_rowstart[row], end = g_rowstart[row + 1];
            int n = end - beg, npair = n >> 1;
            // half-warp h processes edges beg+2i+h; lane owns cols 4p..4p+3
            ull alo = 0ull, ahi = 0ull, blo = 0ull, bhi = 0ull;
            int i = 0;
            int base = beg + half;
            for (; i + 4 <= npair; i += 4) {       // 8 edges in flight/warp
                int e0 = base + 2 * i;
                int j0 = g_esrc[e0], j1 = g_esrc[e0 + 2];
                int j2 = g_esrc[e0 + 4], j3 = g_esrc[e0 + 6];
                ull v0 = gu[j0 * 16 + p];
                ull v1 = gu[j1 * 16 + p];
                ull v2 = gu[j2 * 16 + p];
                ull v3 = gu[j3 * 16 + p];
                acc8(v0, alo, ahi); acc8(v1, blo, bhi);
                acc8(v2, alo, ahi); acc8(v3, blo, bhi);
            }
            for (; i < npair; i++) {
                ull v = gu[g_esrc[base + 2 * i] * 16 + p];
                acc8(v, alo, ahi);
            }
            if ((n & 1) && half == 0) {            // odd tail: half 0 only
                ull v = gu[g_esrc[end - 1] * 16 + p];
                acc8(v, alo, ahi);
            }
            __syncwarp();
            ADD2(alo, alo, blo); ADD2(ahi, ahi, bhi);
            // combine the two half-warps: own + peer (xor 16)
            ull plo = __shfl_xor_sync(~0u, alo, 16);
            ull phi = __shfl_xor_sync(~0u, ahi, 16);
            ADD2(alo, alo, plo);
            ADD2(ahi, ahi, phi);
            // redistribute 4-col ownership -> 2-col packed pair per lane
            int src = lane >> 1;
            ull sl  = __shfl_sync(~0u, alo, src);
            ull shv = __shfl_sync(~0u, ahi, src);
            ull gacc = (lane & 1) ? shv : sl;
            // self term (fp32 exact)
            ull a0 = x2[row * 32 + lane];
            ADD2(a0, a0, gacc);
            unsigned lo, hi; UNPK2(lo, hi, a0);
            ax[r] = __uint_as_float(lo); ay[r] = __uint_as_float(hi);
        }

        ull acc[ROWS];
        warp_gemm4(Ws, bb, ax, ay, acc, lane);

#pragma unroll
        for (int r = 0; r < ROWS; r++) {
            y2[(row0 + r) * 32 + lane] = acc[r];
            unsigned u0, u1; UNPK2(u0, u1, acc[r]);
            float o0 = __uint_as_float(u0), o1 = __uint_as_float(u1);
            s0 += o0; s1 += o1; q0 += o0 * o0; q1 += o1 * o1;
        }
    }

    ssum[w][2 * lane] = s0; ssum[w][2 * lane + 1] = s1;
    ssq[w][2 * lane]  = q0; ssq[w][2 * lane + 1]  = q1;
    __syncthreads();
    if (tid < D) {
        float S = 0.f, Q = 0.f;
#pragma unroll
        for (int ww = 0; ww < WPB; ww++) { S += ssum[ww][tid]; Q += ssq[ww][tid]; }
        g_partial[blockIdx.x * 128 + tid]      = S;
        g_partial[blockIdx.x * 128 + 64 + tid] = Q;
    }
}

// ---------------- K2: BN finalize (64 blocks) + reset barrier counters ------
__global__ void bn_finalize(const float* __restrict__ g, const float* __restrict__ beta) {
    __shared__ float sS[4], sQ[4];
    int c = blockIdx.x;
    int tid = threadIdx.x, lane = tid & 31, w = tid >> 5;
    if (c == 0 && tid < 4) g_bar[tid] = 0;   // reset for next launch sequence
    float S = 0.f, Q = 0.f;
    for (int b = tid; b < NB_F; b += 128) {
        S += g_partial[b * 128 + c];
        Q += g_partial[b * 128 + 64 + c];
    }
#pragma unroll
    for (int off = 16; off > 0; off >>= 1) {
        S += __shfl_down_sync(~0u, S, off);
        Q += __shfl_down_sync(~0u, Q, off);
    }
    if (lane == 0) { sS[w] = S; sQ[w] = Q; }
    __syncthreads();
    if (tid == 0) {
        float St = sS[0] + sS[1] + sS[2] + sS[3];
        float Qt = sQ[0] + sQ[1] + sQ[2] + sQ[3];
        float inv = 1.0f / (float)N_NODES;
        float mean = St * inv;
        float var  = Qt * inv - mean * mean;
        float sc = g[c] * rsqrtf(var + BN_EPS);
        g_bnscale[c] = sc;
        g_bnshift[c] = beta[c] - mean * sc;
    }
}

// ---------------- K3: BN-apply + ReLU + GEMM W2 + ReLU (+fp16 copy) ---------
__global__ void __launch_bounds__(THREADS, 4)
gin_fused2(const float* __restrict__ W2, const float* __restrict__ b2,
           float* __restrict__ out, int write16) {
    __shared__ ull Ws[D * 32];
    int tid = threadIdx.x, w = tid >> 5, lane = tid & 31;

    const ull* W2p = (const ull*)W2;
    for (int i = tid; i < D * 32; i += THREADS) Ws[i] = W2p[i];
    ull bb = ((const ull*)b2)[lane];
    ull sc = ((const ull*)g_bnscale)[lane];
    ull sh = ((const ull*)g_bnshift)[lane];
    __syncthreads();

    const ull* y2 = (const ull*)g_y;
    float2*    o2 = (float2*)out;

    int gid0 = blockIdx.x * WPB + w;
    const int GSTRIDE = NB_F * WPB;

    for (int gid = gid0; gid < NGROUPS; gid += GSTRIDE) {
        int row0 = gid * ROWS;
        float ax[ROWS], ay[ROWS];
#pragma unroll
        for (int r = 0; r < ROWS; r++) {
            ull v = y2[(row0 + r) * 32 + lane];
            ull tt; FMA2(tt, v, sc, sh);
            unsigned lo, hi; UNPK2(lo, hi, tt);
            ax[r] = fmaxf(__uint_as_float(lo), 0.f);
            ay[r] = fmaxf(__uint_as_float(hi), 0.f);
        }

        ull acc[ROWS];
        warp_gemm4(Ws, bb, ax, ay, acc, lane);

#pragma unroll
        for (int r = 0; r < ROWS; r++) {
            unsigned u0, u1; UNPK2(u0, u1, acc[r]);
            float o0 = fmaxf(__uint_as_float(u0), 0.f);
            float o1 = fmaxf(__uint_as_float(u1), 0.f);
            o2[(row0 + r) * 32 + lane] = make_float2(o0, o1);
            if (write16)
                g_g16[(row0 + r) * 32 + lane] = __floats2half2_rn(o0, o1);
        }
    }
}

// ---------------- launch -----------------------------------------------------
extern "C" void kernel_launch(void* const* d_in, const int* in_sizes, int n_in,
                              void* d_out, int out_size) {
    const float* x     = (const float*)d_in[0];
    const void*  ei    = d_in[1];
    const float* W1_0  = (const float*)d_in[2];
    const float* b1_0  = (const float*)d_in[3];
    const float* g_0   = (const float*)d_in[4];
    const float* be_0  = (const float*)d_in[5];
    const float* W2_0  = (const float*)d_in[6];
    const float* b2_0  = (const float*)d_in[7];
    const float* W1_1  = (const float*)d_in[8];
    const float* b1_1  = (const float*)d_in[9];
    const float* g_1   = (const float*)d_in[10];
    const float* be_1  = (const float*)d_in[11];
    const float* W2_1  = (const float*)d_in[12];
    const float* b2_1  = (const float*)d_in[13];

    float* out = (float*)d_out;
    float* h1  = out;
    float* h2  = out + (size_t)N_NODES * D;

    build_kernel<<<HS_B, 256>>>(ei, x);                // 1  (init+cvt+CSR)
    gin_fused1<<<NB_F, THREADS>>>(x, W1_0, b1_0);      // 2
    bn_finalize<<<D, 128>>>(g_0, be_0);                // 3
    gin_fused2<<<NB_F, THREADS>>>(W2_0, b2_0, h1, 1);  // 4  <- profiled
    gin_fused1<<<NB_F, THREADS>>>(h1, W1_1, b1_1);     // 5
    bn_finalize<<<D, 128>>>(g_1, be_1);                // 6
    gin_fused2<<<NB_F, THREADS>>>(W2_1, b2_1, h2, 0);  // 7
}

// round 16
// speedup vs baseline: 1.5121x; 1.5121x over previous
#include <cuda_runtime.h>
#include <cuda_fp16.h>

#define N_NODES 50000
#define N_EDGES 800000
#define D 64
#define BN_EPS 1e-5f
#define THREADS 256
#define WPB 8
#define NB_F 592             // 148 SMs * 4 CTAs
#define ROWS 4               // rows per warp per group
#define NGROUPS (N_NODES / ROWS)   // 12500
#define HS_B 592             // hist_scan_scatter grid (all-resident: 148*4)
#define SCAN_BLK 196         // 196*256 >= N_NODES
#define MAXE 6               // ceil(N_EDGES / (HS_B*256))

typedef unsigned long long ull;

// packed f32x2 helpers (sm_103a FFMA2 path)
#define FMA2(o, a, b, c) asm("fma.rn.f32x2 %0, %1, %2, %3;" : "=l"(o) : "l"(a), "l"(b), "l"(c))
#define ADD2(o, a, b)    asm("add.rn.f32x2 %0, %1, %2;"     : "=l"(o) : "l"(a), "l"(b))
#define PACK2(o, lo, hi) asm("mov.b64 %0, {%1, %2};"        : "=l"(o) : "r"(lo), "r"(hi))
#define UNPK2(lo, hi, i) asm("mov.b64 {%0, %1}, %2;"        : "=r"(lo), "=r"(hi) : "l"(i))

// ---------------- scratch (static device allocations; no cudaMalloc) --------
__device__ int      g_i64;
__device__ int      g_rowstart[N_NODES + 1];
__device__ int      g_cursor[N_NODES];
__device__ int      g_esrc[N_EDGES];
__device__ float    g_y[N_NODES * D];
__device__ float    g_partial[NB_F * 128];
__device__ int      g_blocksum[SCAN_BLK];
__device__ unsigned g_bar[4];                  // grid-barrier counters
__device__ __align__(128) __half2 g_g16[N_NODES * 32];  // fp16 gather source
__device__ __align__(16) float g_bnscale[D];
__device__ __align__(16) float g_bnshift[D];

// ---------------- init: zero state + detect edge_index dtype ----------------
__global__ void init_kernel(const void* ei) {
    int stride = gridDim.x * blockDim.x;
    int gt = blockIdx.x * blockDim.x + threadIdx.x;
    for (int i = gt; i < N_NODES; i += stride) g_rowstart[i] = 0;
    if (gt < 4) g_bar[gt] = 0;
    if (blockIdx.x == 0) {
        __shared__ int any_nonzero;
        if (threadIdx.x == 0) { any_nonzero = 0; g_rowstart[N_NODES] = N_EDGES; }
        __syncthreads();
        const int* w = (const int*)ei;
        for (int i = threadIdx.x; i < 1024; i += blockDim.x)
            if (w[2 * i + 1] != 0) any_nonzero = 1;
        __syncthreads();
        if (threadIdx.x == 0) g_i64 = (any_nonzero == 0) ? 1 : 0;
    }
}

// ---------------- grid barrier (all HS_B CTAs resident) ---------------------
__device__ __forceinline__ void grid_bar(unsigned* ctr) {
    __syncthreads();
    if (threadIdx.x == 0) {
        __threadfence();
        atomicAdd(ctr, 1u);
        while (atomicAdd(ctr, 0u) < (unsigned)HS_B) { }
    }
    __syncthreads();
    __threadfence();
}

// ---------------- hist + scan + scatter: one persistent kernel --------------
__global__ void __launch_bounds__(256, 4) hist_scan_scatter(const void* ei) {
    const bool i64 = (g_i64 != 0);
    const int* p32 = (const int*)ei;
    int tid = threadIdx.x, b = blockIdx.x;
    const int gstride = HS_B * 256;
    int gt = b * 256 + tid;

    // phase 1: histogram of dst; cache src+dst in registers for phase 4
    int dcache[MAXE], scache[MAXE];
#pragma unroll
    for (int k = 0; k < MAXE; k++) {
        int e = gt + k * gstride;
        if (e < N_EDGES) {
            int d = i64 ? p32[2 * (N_EDGES + e)] : p32[N_EDGES + e];
            int s = i64 ? p32[2 * e]             : p32[e];
            dcache[k] = d; scache[k] = s;
            atomicAdd(&g_rowstart[d], 1);
        }
    }
    grid_bar(&g_bar[0]);

    __shared__ int wsum[8];
    __shared__ int sbs[SCAN_BLK];
    __shared__ int blockoff_s;
    int excl_local = 0;
    if (b < SCAN_BLK) {
        int i = b * 256 + tid;
        int v = (i < N_NODES) ? g_rowstart[i] : 0;
        int lane = tid & 31, w = tid >> 5;
        int inc = v;
#pragma unroll
        for (int off = 1; off < 32; off <<= 1) {
            int n = __shfl_up_sync(~0u, inc, off);
            if (lane >= off) inc += n;
        }
        if (lane == 31) wsum[w] = inc;
        __syncthreads();
        if (w == 0) {
            int s = (lane < 8) ? wsum[lane] : 0;
#pragma unroll
            for (int off = 1; off < 8; off <<= 1) {
                int n = __shfl_up_sync(~0u, s, off);
                if (lane >= off) s += n;
            }
            if (lane < 8) wsum[lane] = s;
        }
        __syncthreads();
        int warpoff = (w == 0) ? 0 : wsum[w - 1];
        excl_local = warpoff + inc - v;
        if (tid == 0) g_blocksum[b] = wsum[7];
    }
    grid_bar(&g_bar[1]);

    if (b < SCAN_BLK) {
        for (int j = tid; j < SCAN_BLK; j += 256) sbs[j] = g_blocksum[j];
        __syncthreads();
        if (tid == 0) {
            int o = 0;
            for (int j = 0; j < b; j++) o += sbs[j];
            blockoff_s = o;
        }
        __syncthreads();
        int i = b * 256 + tid;
        if (i < N_NODES) {
            int e0 = blockoff_s + excl_local;
            g_rowstart[i] = e0;
            g_cursor[i]   = e0;
        }
    }
    grid_bar(&g_bar[2]);

    // phase 4: scatter cached src ids into CSR order (no edge re-read)
#pragma unroll
    for (int k = 0; k < MAXE; k++) {
        int e = gt + k * gstride;
        if (e < N_EDGES) {
            int pos = atomicAdd(&g_cursor[dcache[k]], 1);
            g_esrc[pos] = scache[k];
        }
    }
}

// ---------------- fp16 conversion of gather source --------------------------
__global__ void cvt16_kernel(const float* __restrict__ src) {
    const float2* s2 = (const float2*)src;
    int stride = gridDim.x * blockDim.x;
    for (int i = blockIdx.x * blockDim.x + threadIdx.x; i < N_NODES * 32; i += stride)
        g_g16[i] = __float22half2_rn(s2[i]);
}

// convert 8B (2 half2 = 4 cols) and accumulate into two packed f32 pairs
__device__ __forceinline__ void acc8(ull v, ull& alo, ull& ahi) {
    unsigned lo32 = (unsigned)v, hi32 = (unsigned)(v >> 32);
    __half2 hl = *(__half2*)&lo32, hh = *(__half2*)&hi32;
    float2 f0 = __half22float2(hl), f1 = __half22float2(hh);
    ull u0, u1;
    PACK2(u0, __float_as_uint(f0.x), __float_as_uint(f0.y));
    PACK2(u1, __float_as_uint(f1.x), __float_as_uint(f1.y));
    ADD2(alo, alo, u0);
    ADD2(ahi, ahi, u1);
}

// ---- GEMM core: 4 rows per warp, h in registers, shuffle broadcast ---------
__device__ __forceinline__ void warp_gemm4(const ull* __restrict__ Ws, ull bb,
                                           const float* ax, const float* ay,
                                           ull* acc, int lane) {
    acc[0] = bb; acc[1] = bb; acc[2] = bb; acc[3] = bb;
#pragma unroll
    for (int k = 0; k < D; k++) {
        ull wv = Ws[k * 32 + lane];
#pragma unroll
        for (int r = 0; r < ROWS; r++) {
            float hv = __shfl_sync(~0u, (k & 1) ? ay[r] : ax[r], k >> 1);
            unsigned hu = __float_as_uint(hv);
            ull h2; PACK2(h2, hu, hu);
            FMA2(acc[r], h2, wv, acc[r]);
        }
    }
}

// ---------------- K1: paired-lane fp16 gather + GEMM W1 + BN partials -------
__global__ void __launch_bounds__(THREADS, 4)
gin_fused1(const float* __restrict__ xin, const float* __restrict__ W1,
           const float* __restrict__ b1) {
    __shared__ ull Ws[D * 32];
    __shared__ float ssum[WPB][D];
    __shared__ float ssq[WPB][D];
    int tid = threadIdx.x, w = tid >> 5, lane = tid & 31;
    int half = lane >> 4, p = lane & 15;

    const ull* W1p = (const ull*)W1;
    for (int i = tid; i < D * 32; i += THREADS) Ws[i] = W1p[i];
    ull bb = ((const ull*)b1)[lane];
    __syncthreads();

    const ull* x2 = (const ull*)xin;
    const ull* gu = (const ull*)g_g16;   // gu[row*16+p] = cols 4p..4p+3 (fp16)
    ull*       y2 = (ull*)g_y;

    float s0 = 0.f, s1 = 0.f, q0 = 0.f, q1 = 0.f;
    int gid0 = blockIdx.x * WPB + w;
    const int GSTRIDE = NB_F * WPB;      // 4736

    for (int gid = gid0; gid < NGROUPS; gid += GSTRIDE) {
        int row0 = gid * ROWS;
        float ax[ROWS], ay[ROWS];

#pragma unroll
        for (int r = 0; r < ROWS; r++) {
            int row = row0 + r;
            int beg = g_rowstart[row], end = g_rowstart[row + 1];
            int n = end - beg, npair = n >> 1;
            // half-warp h processes edges beg+2i+h; lane owns cols 4p..4p+3
            ull alo = 0ull, ahi = 0ull, blo = 0ull, bhi = 0ull;
            int i = 0;
            int base = beg + half;
            for (; i + 4 <= npair; i += 4) {       // 8 edges in flight/warp
                int e0 = base + 2 * i;
                int j0 = g_esrc[e0], j1 = g_esrc[e0 + 2];
                int j2 = g_esrc[e0 + 4], j3 = g_esrc[e0 + 6];
                ull v0 = gu[j0 * 16 + p];
                ull v1 = gu[j1 * 16 + p];
                ull v2 = gu[j2 * 16 + p];
                ull v3 = gu[j3 * 16 + p];
                acc8(v0, alo, ahi); acc8(v1, blo, bhi);
                acc8(v2, alo, ahi); acc8(v3, blo, bhi);
            }
            for (; i < npair; i++) {
                ull v = gu[g_esrc[base + 2 * i] * 16 + p];
                acc8(v, alo, ahi);
            }
            if ((n & 1) && half == 0) {            // odd tail: half 0 only
                ull v = gu[g_esrc[end - 1] * 16 + p];
                acc8(v, alo, ahi);
            }
            __syncwarp();
            ADD2(alo, alo, blo); ADD2(ahi, ahi, bhi);
            // combine the two half-warps: own + peer (xor 16)
            ull plo = __shfl_xor_sync(~0u, alo, 16);
            ull phi = __shfl_xor_sync(~0u, ahi, 16);
            ADD2(alo, alo, plo);
            ADD2(ahi, ahi, phi);
            // redistribute 4-col ownership -> 2-col packed pair per lane
            int src = lane >> 1;
            ull sl  = __shfl_sync(~0u, alo, src);
            ull shv = __shfl_sync(~0u, ahi, src);
            ull gacc = (lane & 1) ? shv : sl;
            // self term (fp32 exact)
            ull a0 = x2[row * 32 + lane];
            ADD2(a0, a0, gacc);
            unsigned lo, hi; UNPK2(lo, hi, a0);
            ax[r] = __uint_as_float(lo); ay[r] = __uint_as_float(hi);
        }

        ull acc[ROWS];
        warp_gemm4(Ws, bb, ax, ay, acc, lane);

#pragma unroll
        for (int r = 0; r < ROWS; r++) {
            y2[(row0 + r) * 32 + lane] = acc[r];
            unsigned u0, u1; UNPK2(u0, u1, acc[r]);
            float o0 = __uint_as_float(u0), o1 = __uint_as_float(u1);
            s0 += o0; s1 += o1; q0 += o0 * o0; q1 += o1 * o1;
        }
    }

    ssum[w][2 * lane] = s0; ssum[w][2 * lane + 1] = s1;
    ssq[w][2 * lane]  = q0; ssq[w][2 * lane + 1]  = q1;
    __syncthreads();
    if (tid < D) {
        float S = 0.f, Q = 0.f;
#pragma unroll
        for (int ww = 0; ww < WPB; ww++) { S += ssum[ww][tid]; Q += ssq[ww][tid]; }
        g_partial[blockIdx.x * 128 + tid]      = S;
        g_partial[blockIdx.x * 128 + 64 + tid] = Q;
    }
}

// ---------------- K2: BN finalize (64 blocks, one per column) ---------------
__global__ void bn_finalize(const float* __restrict__ g, const float* __restrict__ beta) {
    __shared__ float sS[4], sQ[4];
    int c = blockIdx.x;
    int tid = threadIdx.x, lane = tid & 31, w = tid >> 5;
    float S = 0.f, Q = 0.f;
    for (int b = tid; b < NB_F; b += 128) {
        S += g_partial[b * 128 + c];
        Q += g_partial[b * 128 + 64 + c];
    }
#pragma unroll
    for (int off = 16; off > 0; off >>= 1) {
        S += __shfl_down_sync(~0u, S, off);
        Q += __shfl_down_sync(~0u, Q, off);
    }
    if (lane == 0) { sS[w] = S; sQ[w] = Q; }
    __syncthreads();
    if (tid == 0) {
        float St = sS[0] + sS[1] + sS[2] + sS[3];
        float Qt = sQ[0] + sQ[1] + sQ[2] + sQ[3];
        float inv = 1.0f / (float)N_NODES;
        float mean = St * inv;
        float var  = Qt * inv - mean * mean;
        float sc = g[c] * rsqrtf(var + BN_EPS);
        g_bnscale[c] = sc;
        g_bnshift[c] = beta[c] - mean * sc;
    }
}

// ---------------- K3: BN-apply + ReLU + GEMM W2 + ReLU (+fp16 copy) ---------
__global__ void __launch_bounds__(THREADS, 4)
gin_fused2(const float* __restrict__ W2, const float* __restrict__ b2,
           float* __restrict__ out, int write16) {
    __shared__ ull Ws[D * 32];
    int tid = threadIdx.x, w = tid >> 5, lane = tid & 31;

    const ull* W2p = (const ull*)W2;
    for (int i = tid; i < D * 32; i += THREADS) Ws[i] = W2p[i];
    ull bb = ((const ull*)b2)[lane];
    ull sc = ((const ull*)g_bnscale)[lane];
    ull sh = ((const ull*)g_bnshift)[lane];
    __syncthreads();

    const ull* y2 = (const ull*)g_y;
    float2*    o2 = (float2*)out;

    int gid0 = blockIdx.x * WPB + w;
    const int GSTRIDE = NB_F * WPB;

    for (int gid = gid0; gid < NGROUPS; gid += GSTRIDE) {
        int row0 = gid * ROWS;
        float ax[ROWS], ay[ROWS];
#pragma unroll
        for (int r = 0; r < ROWS; r++) {
            ull v = y2[(row0 + r) * 32 + lane];
            ull tt; FMA2(tt, v, sc, sh);
            unsigned lo, hi; UNPK2(lo, hi, tt);
            ax[r] = fmaxf(__uint_as_float(lo), 0.f);
            ay[r] = fmaxf(__uint_as_float(hi), 0.f);
        }

        ull acc[ROWS];
        warp_gemm4(Ws, bb, ax, ay, acc, lane);

#pragma unroll
        for (int r = 0; r < ROWS; r++) {
            unsigned u0, u1; UNPK2(u0, u1, acc[r]);
            float o0 = fmaxf(__uint_as_float(u0), 0.f);
            float o1 = fmaxf(__uint_as_float(u1), 0.f);
            o2[(row0 + r) * 32 + lane] = make_float2(o0, o1);
            if (write16)
                g_g16[(row0 + r) * 32 + lane] = __floats2half2_rn(o0, o1);
        }
    }
}

// ---------------- launch -----------------------------------------------------
extern "C" void kernel_launch(void* const* d_in, const int* in_sizes, int n_in,
                              void* d_out, int out_size) {
    const float* x     = (const float*)d_in[0];
    const void*  ei    = d_in[1];
    const float* W1_0  = (const float*)d_in[2];
    const float* b1_0  = (const float*)d_in[3];
    const float* g_0   = (const float*)d_in[4];
    const float* be_0  = (const float*)d_in[5];
    const float* W2_0  = (const float*)d_in[6];
    const float* b2_0  = (const float*)d_in[7];
    const float* W1_1  = (const float*)d_in[8];
    const float* b1_1  = (const float*)d_in[9];
    const float* g_1   = (const float*)d_in[10];
    const float* be_1  = (const float*)d_in[11];
    const float* W2_1  = (const float*)d_in[12];
    const float* b2_1  = (const float*)d_in[13];

    float* out = (float*)d_out;
    float* h1  = out;
    float* h2  = out + (size_t)N_NODES * D;

    init_kernel<<<208, 256>>>(ei);                     // 1
    hist_scan_scatter<<<HS_B, 256>>>(ei);              // 2
    cvt16_kernel<<<208, 256>>>(x);                     // 3

    gin_fused1<<<NB_F, THREADS>>>(x, W1_0, b1_0);      // 4  <- profiled
    bn_finalize<<<D, 128>>>(g_0, be_0);                // 5
    gin_fused2<<<NB_F, THREADS>>>(W2_0, b2_0, h1, 1);  // 6

    gin_fused1<<<NB_F, THREADS>>>(h1, W1_1, b1_1);     // 7
    bn_finalize<<<D, 128>>>(g_1, be_1);                // 8
    gin_fused2<<<NB_F, THREADS>>>(W2_1, b2_1, h2, 0);  // 9
}